// round 13
// baseline (speedup 1.0000x reference)
#include <cuda_runtime.h>
#include <math.h>

#define BB 128
#define NN 256
#define MM (BB*NN)
#define KNBR 16
#define BN_SCALE_F 0.99999500003749969f

// ---------------- scratch (device globals; no allocation allowed) ----------
__device__ float g_U[MM * 256];
__device__ float g_V[MM * 256];
__device__ float g_h1[MM * 64];
__device__ float g_h2[MM * 128];
__device__ int   g_idx[MM * KNBR];
__device__ float g_p[BB * 256];

// knn smem: BsD 2*2080 + sqb 256 + D2s 32*260 = 12736 floats = 50944 B
#define FAT_SMEM_FLOATS 12736
#define FAT_SMEM_BYTES  (FAT_SMEM_FLOATS * 4)

// ---------------- tf32 helpers ---------------------------------------------
__device__ __forceinline__ unsigned f2tf32(float x) {
    unsigned r;
    asm("cvt.rna.tf32.f32 %0, %1;" : "=r"(r) : "f"(x));
    return r;
}

#define MMA_TF32(d0,d1,d2,d3,a0,a1,a2,a3,b0,b1)                               \
  asm volatile("mma.sync.aligned.m16n8k8.row.col.f32.tf32.tf32.f32 "          \
      "{%0,%1,%2,%3}, {%4,%5,%6,%7}, {%8,%9}, {%0,%1,%2,%3};"                 \
      : "+f"(d0), "+f"(d1), "+f"(d2), "+f"(d3)                                \
      : "r"(a0), "r"(a1), "r"(a2), "r"(a3), "r"(b0), "r"(b1))

// ===== tiled kNN body: 32-row tiles, dist GEMM + 8-way select ==============
// acc[4][8] (32 regs) keeps fat kernels at 3 blocks/SM. 1024 blocks/layer.
template<int K, bool PAD6>
__device__ __forceinline__ void knn_body(const float* __restrict__ X,
                                         int* __restrict__ idx_out,
                                         int bid, float* sm) {
    float* BsD = sm;              // [2][8][260]
    float* sqb = sm + 4160;       // [256]
    float* D2s = sm + 4416;       // [32][260]
    const int b  = bid >> 3;
    const int m0 = (bid & 7) * 32;
    const int t  = threadIdx.x;
    const int KS = PAD6 ? 6 : K;
    const float* Xb = X + (size_t)b * NN * KS;
    const int tn = t & 31, w = t >> 5;      // lane cols {tn*4, 128+tn*4}; warp rows w*4..+3

    float acc[4][8] = {};
    float snorm = 0.f;

    auto load_chunk = [&](int k0, float4& a, float4& c) {
        if (PAD6) {
            const float* s = Xb + t * 6;
            float2 p0 = *reinterpret_cast<const float2*>(s);
            float2 p1 = *reinterpret_cast<const float2*>(s + 2);
            float2 p2 = *reinterpret_cast<const float2*>(s + 4);
            a = make_float4(p0.x, p0.y, p1.x, p1.y);
            c = make_float4(p2.x, p2.y, 0.f, 0.f);
        } else {
            a = *reinterpret_cast<const float4*>(&Xb[(size_t)t * K + k0]);
            c = *reinterpret_cast<const float4*>(&Xb[(size_t)t * K + k0 + 4]);
        }
    };
    auto stage = [&](int buf, const float4& a, const float4& c) {
        float* B = BsD + buf * 2080;
        B[0 * 260 + t] = a.x; B[1 * 260 + t] = a.y;
        B[2 * 260 + t] = a.z; B[3 * 260 + t] = a.w;
        B[4 * 260 + t] = c.x; B[5 * 260 + t] = c.y;
        B[6 * 260 + t] = c.z; B[7 * 260 + t] = c.w;
    };
    auto compute = [&](int pb) {
        const float* B = BsD + pb * 2080;
        #pragma unroll
        for (int k = 0; k < 8; ++k) {
            float4 a4 = *reinterpret_cast<const float4*>(&B[k * 260 + m0 + w * 4]); // broadcast
            float4 b0 = *reinterpret_cast<const float4*>(&B[k * 260 + tn * 4]);
            float4 b1 = *reinterpret_cast<const float4*>(&B[k * 260 + 128 + tn * 4]);
            float av[4] = {a4.x, a4.y, a4.z, a4.w};
            float bv[8] = {b0.x, b0.y, b0.z, b0.w, b1.x, b1.y, b1.z, b1.w};
            #pragma unroll
            for (int i = 0; i < 4; ++i) {
                #pragma unroll
                for (int c = 0; c < 8; ++c)
                    acc[i][c] += av[i] * bv[c];
            }
        }
    };

    float4 v0, v1;
    load_chunk(0, v0, v1);
    snorm += v0.x*v0.x + v0.y*v0.y + v0.z*v0.z + v0.w*v0.w
           + v1.x*v1.x + v1.y*v1.y + v1.z*v1.z + v1.w*v1.w;
    stage(0, v0, v1);
    __syncthreads();

    const int NCH = PAD6 ? 1 : K / 8;
    for (int ci = 1; ci < NCH; ++ci) {
        float4 n0_, n1_;
        load_chunk(ci * 8, n0_, n1_);
        compute((ci - 1) & 1);
        snorm += n0_.x*n0_.x + n0_.y*n0_.y + n0_.z*n0_.z + n0_.w*n0_.w
               + n1_.x*n1_.x + n1_.y*n1_.y + n1_.z*n1_.z + n1_.w*n1_.w;
        stage(ci & 1, n0_, n1_);
        __syncthreads();
    }
    compute((NCH - 1) & 1);
    sqb[t] = snorm;
    __syncthreads();

    // epilogue: d2 = |i|^2 + |j|^2 - 2 dot -> smem tile (local rows w*4..+3)
    #pragma unroll
    for (int i = 0; i < 4; ++i) {
        const int lr = w * 4 + i;
        const float si = sqb[m0 + lr];
        float4 o0, o1;
        o0.x = si + sqb[tn*4+0]     - 2.f * acc[i][0];
        o0.y = si + sqb[tn*4+1]     - 2.f * acc[i][1];
        o0.z = si + sqb[tn*4+2]     - 2.f * acc[i][2];
        o0.w = si + sqb[tn*4+3]     - 2.f * acc[i][3];
        o1.x = si + sqb[128+tn*4+0] - 2.f * acc[i][4];
        o1.y = si + sqb[128+tn*4+1] - 2.f * acc[i][5];
        o1.z = si + sqb[128+tn*4+2] - 2.f * acc[i][6];
        o1.w = si + sqb[128+tn*4+3] - 2.f * acc[i][7];
        *reinterpret_cast<float4*>(&D2s[lr * 260 + tn * 4])       = o0;
        *reinterpret_cast<float4*>(&D2s[lr * 260 + 128 + tn * 4]) = o1;
    }
    __syncthreads();

    if (t < 32) D2s[t * 260 + m0 + t] = INFINITY;   // poison self
    __syncthreads();

    // ---- top-16: 8 threads per row, contiguous 32-col chunks ----
    const int r = t >> 3, q = t & 7;
    float bd[KNBR]; int bj[KNBR];
    #pragma unroll
    for (int s = 0; s < KNBR; ++s) { bd[s] = INFINITY; bj[s] = -1; }

    #pragma unroll
    for (int j4 = 0; j4 < 8; ++j4) {
        float4 v = *reinterpret_cast<const float4*>(&D2s[r * 260 + q * 32 + j4 * 4]);
        float dv[4] = {v.x, v.y, v.z, v.w};
        #pragma unroll
        for (int e = 0; e < 4; ++e) {
            const float d2 = dv[e];
            if (d2 < bd[KNBR - 1]) {
                const int j = q * 32 + j4 * 4 + e;
                float nd = d2; int nj = j;
                #pragma unroll
                for (int s = 0; s < KNBR; ++s) {
                    if (nd < bd[s]) {
                        float td = bd[s]; int tj = bj[s];
                        bd[s] = nd; bj[s] = nj; nd = td; nj = tj;
                    }
                }
            }
        }
    }
    __syncthreads();                             // reuse D2s for lists
    float* sd = D2s;                             // [32*8][16]
    int*   si = reinterpret_cast<int*>(D2s + 4096);
    #pragma unroll
    for (int s = 0; s < KNBR; ++s) {
        sd[(r * 8 + q) * 16 + s] = bd[s];
        si[(r * 8 + q) * 16 + s] = bj[s];
    }
    __syncthreads();

    if (q == 0) {
        float fd[KNBR]; int fj[KNBR];
        #pragma unroll
        for (int s = 0; s < KNBR; ++s) { fd[s] = INFINITY; fj[s] = -1; }
        // ascending chunk order, each sorted ascending; strict < insert keeps
        // the lower-index candidate on exact ties (lax.top_k semantics).
        for (int qq = 0; qq < 8; ++qq) {
            for (int s = 0; s < KNBR; ++s) {
                float d = sd[(r * 8 + qq) * 16 + s];
                if (!(d < fd[KNBR - 1])) break;
                int nj = si[(r * 8 + qq) * 16 + s];
                float nd = d;
                #pragma unroll
                for (int s2 = 0; s2 < KNBR; ++s2) {
                    if (nd < fd[s2]) {
                        float td = fd[s2]; int tj = fj[s2];
                        fd[s2] = nd; fj[s2] = nj; nd = td; nj = tj;
                    }
                }
            }
        }
        #pragma unroll
        for (int s = 0; s < KNBR; ++s)
            idx_out[((size_t)b * NN + m0 + r) * KNBR + s] = fj[s];
    }
}

// ---------------- layer-1 U/V body (K=6, C=64): 32 points per block --------
__device__ __forceinline__ void uv1_body(const float* __restrict__ X,
                                         const float* __restrict__ W,
                                         float* __restrict__ U,
                                         float* __restrict__ V,
                                         int bid2, float* sm) {
    float* Ws = sm;
    const int t = threadIdx.x;
    for (int e = t; e < 12 * 64; e += 256) Ws[e] = W[e];
    __syncthreads();
    const int c = t & 63, pp = t >> 6;
    const int m0 = bid2 * 32;
    #pragma unroll
    for (int i = 0; i < 8; ++i) {
        const int m = m0 + i * 4 + pp;
        const float* x = X + (size_t)m * 6;
        float u = 0.f, v = 0.f;
        #pragma unroll
        for (int d = 0; d < 6; ++d) {
            float xd = x[d];
            u += xd * Ws[d * 64 + c];
            v += xd * Ws[(6 + d) * 64 + c];
        }
        U[(size_t)m * 64 + c] = u;
        V[(size_t)m * 64 + c] = v;
    }
}

// ---- U/V GEMM body (fp32): BM=128 BN=64 BK=8, 8x4/thread, dbl-buffered ----
// acc[8][4] = 32 regs keeps the fat kernel at 3 blocks/SM.
template<int K>
__device__ __forceinline__ void uv_body84(const float* __restrict__ X,
                                          const float* __restrict__ W,
                                          const int C, float* __restrict__ U,
                                          float* __restrict__ V,
                                          int bx, int by, float* sm) {
    float* As = sm;                  // [2][8][132]
    float* Wt = sm + 2112;           // [2][8][68]
    const int t = threadIdx.x;
    const int m0 = bx * 128;
    const int nt = C / 64;
    const bool isU = by < nt;
    const int n0 = (isU ? by : by - nt) * 64;
    const float* Wb = W + (isU ? (size_t)0 : (size_t)K * C);
    float* Out = isU ? U : V;

    const int am = t >> 1, ak = (t & 1) * 4;      // A loader (256 thr)
    const int wk = t >> 4, wn = (t & 15) * 4;     // W loader (t < 128)
    const int tx = t & 15, ty = t >> 4;           // compute: rows ty*8, cols tx*4

    float acc[8][4] = {};

    auto stage = [&](int buf, const float4& xa, const float4& wa) {
        float* A = As + buf * 1056;
        A[(ak + 0) * 132 + am] = xa.x; A[(ak + 1) * 132 + am] = xa.y;
        A[(ak + 2) * 132 + am] = xa.z; A[(ak + 3) * 132 + am] = xa.w;
        if (t < 128)
            *reinterpret_cast<float4*>(&Wt[buf * 544 + wk * 68 + wn]) = wa;
    };
    auto compute = [&](int pb) {
        const float* A = As + pb * 1056;
        const float* Wp = Wt + pb * 544;
        #pragma unroll
        for (int k = 0; k < 8; ++k) {
            float4 a0 = *reinterpret_cast<const float4*>(&A[k * 132 + ty * 8]);
            float4 a1 = *reinterpret_cast<const float4*>(&A[k * 132 + ty * 8 + 4]);
            float4 b0 = *reinterpret_cast<const float4*>(&Wp[k * 68 + tx * 4]);
            float av[8] = {a0.x, a0.y, a0.z, a0.w, a1.x, a1.y, a1.z, a1.w};
            float bv[4] = {b0.x, b0.y, b0.z, b0.w};
            #pragma unroll
            for (int i = 0; i < 8; ++i) {
                #pragma unroll
                for (int c = 0; c < 4; ++c)
                    acc[i][c] += av[i] * bv[c];
            }
        }
    };

    float4 xa = *reinterpret_cast<const float4*>(&X[(size_t)(m0 + am) * K + ak]);
    float4 wa = (t < 128)
        ? *reinterpret_cast<const float4*>(&Wb[(size_t)wk * C + n0 + wn])
        : make_float4(0.f, 0.f, 0.f, 0.f);
    stage(0, xa, wa);
    __syncthreads();

    const int NCH = K / 8;
    for (int ci = 1; ci < NCH; ++ci) {
        float4 xn = *reinterpret_cast<const float4*>(
            &X[(size_t)(m0 + am) * K + ci * 8 + ak]);
        float4 wnx = (t < 128)
            ? *reinterpret_cast<const float4*>(&Wb[(size_t)(ci * 8 + wk) * C + n0 + wn])
            : make_float4(0.f, 0.f, 0.f, 0.f);
        compute((ci - 1) & 1);
        stage(ci & 1, xn, wnx);
        __syncthreads();
    }
    compute((NCH - 1) & 1);

    #pragma unroll
    for (int i = 0; i < 8; ++i) {
        *reinterpret_cast<float4*>(&Out[(size_t)(m0 + ty * 8 + i) * C + n0 + tx * 4]) =
            make_float4(acc[i][0], acc[i][1], acc[i][2], acc[i][3]);
    }
}

// ---- uv3 tf32 tensor-core body: K=128, C=256, BM=128, BN=64 (round-12) ----
__device__ __forceinline__ void uv3_tf32_body(const float* __restrict__ X,
                                              const float* __restrict__ W,
                                              float* __restrict__ U,
                                              float* __restrict__ V,
                                              int bx, int by, float* sm) {
    constexpr int K = 128, C = 256;
    unsigned* As = reinterpret_cast<unsigned*>(sm);          // [2][8][132]
    unsigned* Wt = reinterpret_cast<unsigned*>(sm) + 2112;   // [2][8][68]
    const int t = threadIdx.x;
    const int m0 = bx * 128;
    const bool isU = by < 4;
    const int n0 = (by & 3) * 64;
    const float* Wb = W + (isU ? (size_t)0 : (size_t)K * C);
    float* Out = isU ? U : V;

    const int am = t >> 1, ak = (t & 1) * 4;
    const int wk = t >> 4, wn2 = (t & 15) * 4;
    const int lane = t & 31, warp = t >> 5;
    const int gid = lane >> 2, tid4 = lane & 3;
    const int wm = (warp >> 1) * 32, wn = (warp & 1) * 32;

    float acc[2][4][4] = {};

    auto stage = [&](int buf, const float4& xa, const float4& wa) {
        unsigned* A = As + buf * 1056;
        A[(ak + 0) * 132 + am] = f2tf32(xa.x);
        A[(ak + 1) * 132 + am] = f2tf32(xa.y);
        A[(ak + 2) * 132 + am] = f2tf32(xa.z);
        A[(ak + 3) * 132 + am] = f2tf32(xa.w);
        if (t < 128) {
            unsigned* Wp = Wt + buf * 544 + wk * 68 + wn2;
            Wp[0] = f2tf32(wa.x); Wp[1] = f2tf32(wa.y);
            Wp[2] = f2tf32(wa.z); Wp[3] = f2tf32(wa.w);
        }
    };
    auto compute = [&](int pb) {
        const unsigned* A = As + pb * 1056;
        const unsigned* Wp = Wt + pb * 544;
        unsigned a[2][4], bf[4][2];
        #pragma unroll
        for (int mi = 0; mi < 2; ++mi) {
            const int base = wm + mi * 16 + gid;
            a[mi][0] = A[tid4 * 132 + base];
            a[mi][1] = A[tid4 * 132 + base + 8];
            a[mi][2] = A[(tid4 + 4) * 132 + base];
            a[mi][3] = A[(tid4 + 4) * 132 + base + 8];
        }
        #pragma unroll
        for (int ni = 0; ni < 4; ++ni) {
            const int bc = wn + ni * 8 + gid;
            bf[ni][0] = Wp[tid4 * 68 + bc];
            bf[ni][1] = Wp[(tid4 + 4) * 68 + bc];
        }
        #pragma unroll
        for (int mi = 0; mi < 2; ++mi)
            #pragma unroll
            for (int ni = 0; ni < 4; ++ni)
                MMA_TF32(acc[mi][ni][0], acc[mi][ni][1],
                         acc[mi][ni][2], acc[mi][ni][3],
                         a[mi][0], a[mi][1], a[mi][2], a[mi][3],
                         bf[ni][0], bf[ni][1]);
    };

    float4 xa = *reinterpret_cast<const float4*>(&X[(size_t)(m0 + am) * K + ak]);
    float4 wa = (t < 128)
        ? *reinterpret_cast<const float4*>(&Wb[(size_t)wk * C + n0 + wn2])
        : make_float4(0.f, 0.f, 0.f, 0.f);
    stage(0, xa, wa);
    __syncthreads();

    const int NCH = K / 8;
    for (int ci = 1; ci < NCH; ++ci) {
        float4 xn = *reinterpret_cast<const float4*>(
            &X[(size_t)(m0 + am) * K + ci * 8 + ak]);
        float4 wnx = (t < 128)
            ? *reinterpret_cast<const float4*>(&Wb[(size_t)(ci * 8 + wk) * C + n0 + wn2])
            : make_float4(0.f, 0.f, 0.f, 0.f);
        compute((ci - 1) & 1);
        stage(ci & 1, xn, wnx);
        __syncthreads();
    }
    compute((NCH - 1) & 1);

    #pragma unroll
    for (int mi = 0; mi < 2; ++mi) {
        #pragma unroll
        for (int ni = 0; ni < 4; ++ni) {
            const int row = m0 + wm + mi * 16 + gid;
            const int col = n0 + wn + ni * 8 + tid4 * 2;
            *reinterpret_cast<float2*>(&Out[(size_t)row * C + col]) =
                make_float2(acc[mi][ni][0], acc[mi][ni][1]);
            *reinterpret_cast<float2*>(&Out[(size_t)(row + 8) * C + col]) =
                make_float2(acc[mi][ni][2], acc[mi][ni][3]);
        }
    }
}

// ---------------- fat kernels: 3 blocks/SM target --------------------------
__global__ __launch_bounds__(256, 3)
void fatL1(const float* __restrict__ x, const float* __restrict__ W1,
           int* __restrict__ idx, float* __restrict__ U, float* __restrict__ V) {
    extern __shared__ float sm[];
    const int bid = blockIdx.x;
    if (bid < 1024) knn_body<8, true>(x, idx, bid, sm);
    else            uv1_body(x, W1, U, V, bid - 1024, sm);
}

__global__ __launch_bounds__(256, 3)
void fatL2(const float* __restrict__ h1, const float* __restrict__ W2,
           int* __restrict__ idx, float* __restrict__ U, float* __restrict__ V) {
    extern __shared__ float sm[];
    const int bid = blockIdx.x;
    if (bid < 1024) knn_body<64, false>(h1, idx, bid, sm);
    else {
        const int b2 = bid - 1024;                 // [0, 1024): 256 m x 4 (2 n x {U,V})
        uv_body84<64>(h1, W2, 128, U, V, b2 & 255, b2 >> 8, sm);
    }
}

__global__ __launch_bounds__(256, 3)
void fatL3(const float* __restrict__ h2, const float* __restrict__ W3,
           int* __restrict__ idx, float* __restrict__ U, float* __restrict__ V) {
    extern __shared__ float sm[];
    const int bid = blockIdx.x;
    if (bid < 1024) knn_body<128, false>(h2, idx, bid, sm);
    else {
        const int b2 = bid - 1024;                 // [0, 2048)
        uv3_tf32_body(h2, W3, U, V, b2 & 255, b2 >> 8, sm);
    }
}

// -------- neighbor aggregation + BN + ReLU: float4, 4 channels/thread ------
template<int C>
__global__ __launch_bounds__(256)
void agg_kernel(const float* __restrict__ U, const float* __restrict__ V,
                const int* __restrict__ idx, const float* __restrict__ bias,
                const float* __restrict__ g, const float* __restrict__ be,
                float* __restrict__ H) {
    constexpr int CG = C / 4;
    constexpr int PPB = 256 / CG;
    __shared__ int sidx[PPB * KNBR];
    const int p0 = blockIdx.x * PPB;
    const int t = threadIdx.x;
    if (t < PPB * KNBR) sidx[t] = idx[(size_t)p0 * KNBR + t] * C;
    __syncthreads();
    const int lp = t / CG, c4 = (t % CG) * 4;
    const int pt = p0 + lp;
    const int b = pt >> 8;
    const float* Vb4 = V + ((size_t)(b << 8)) * C + c4;
    float4 u = *reinterpret_cast<const float4*>(&U[(size_t)pt * C + c4]);
    float4 v = *reinterpret_cast<const float4*>(&V[(size_t)pt * C + c4]);
    float4 mx = make_float4(-INFINITY, -INFINITY, -INFINITY, -INFINITY);
    float4 mn = make_float4(INFINITY, INFINITY, INFINITY, INFINITY);
    #pragma unroll
    for (int k = 0; k < KNBR; ++k) {
        float4 w = *reinterpret_cast<const float4*>(Vb4 + sidx[lp * KNBR + k]);
        mx.x = fmaxf(mx.x, w.x); mn.x = fminf(mn.x, w.x);
        mx.y = fmaxf(mx.y, w.y); mn.y = fminf(mn.y, w.y);
        mx.z = fmaxf(mx.z, w.z); mn.z = fminf(mn.z, w.z);
        mx.w = fmaxf(mx.w, w.w); mn.w = fminf(mn.w, w.w);
    }
    float4 gv = *reinterpret_cast<const float4*>(&g[c4]);
    float4 bi = *reinterpret_cast<const float4*>(&bias[c4]);
    float4 bev = *reinterpret_cast<const float4*>(&be[c4]);
    float4 o;
    { float a = gv.x * BN_SCALE_F; float m = (a >= 0.f) ? mx.x : mn.x;
      o.x = fmaxf(fmaf(a, u.x - v.x + m + bi.x, bev.x), 0.f); }
    { float a = gv.y * BN_SCALE_F; float m = (a >= 0.f) ? mx.y : mn.y;
      o.y = fmaxf(fmaf(a, u.y - v.y + m + bi.y, bev.y), 0.f); }
    { float a = gv.z * BN_SCALE_F; float m = (a >= 0.f) ? mx.z : mn.z;
      o.z = fmaxf(fmaf(a, u.z - v.z + m + bi.z, bev.z), 0.f); }
    { float a = gv.w * BN_SCALE_F; float m = (a >= 0.f) ? mx.w : mn.w;
      o.w = fmaxf(fmaf(a, u.w - v.w + m + bi.w, bev.w), 0.f); }
    *reinterpret_cast<float4*>(&H[(size_t)pt * C + c4]) = o;
}

// ------- layer-3 agg + global max pool (h >= 0), float4 --------------------
template<int C>
__global__ __launch_bounds__(256)
void agg_pool_kernel(const float* __restrict__ U, const float* __restrict__ V,
                     const int* __restrict__ idx, const float* __restrict__ bias,
                     const float* __restrict__ g, const float* __restrict__ be,
                     int* __restrict__ P) {
    constexpr int CG = C / 4;
    constexpr int PPB = 256 / CG;
    __shared__ int sidx[PPB * KNBR];
    const int p0 = blockIdx.x * PPB;
    const int t = threadIdx.x;
    if (t < PPB * KNBR) sidx[t] = idx[(size_t)p0 * KNBR + t] * C;
    __syncthreads();
    const int lp = t / CG, c4 = (t % CG) * 4;
    const int pt = p0 + lp;
    const int b = pt >> 8;
    const float* Vb4 = V + ((size_t)(b << 8)) * C + c4;
    float4 u = *reinterpret_cast<const float4*>(&U[(size_t)pt * C + c4]);
    float4 v = *reinterpret_cast<const float4*>(&V[(size_t)pt * C + c4]);
    float4 mx = make_float4(-INFINITY, -INFINITY, -INFINITY, -INFINITY);
    float4 mn = make_float4(INFINITY, INFINITY, INFINITY, INFINITY);
    #pragma unroll
    for (int k = 0; k < KNBR; ++k) {
        float4 w = *reinterpret_cast<const float4*>(Vb4 + sidx[lp * KNBR + k]);
        mx.x = fmaxf(mx.x, w.x); mn.x = fminf(mn.x, w.x);
        mx.y = fmaxf(mx.y, w.y); mn.y = fminf(mn.y, w.y);
        mx.z = fmaxf(mx.z, w.z); mn.z = fminf(mn.z, w.z);
        mx.w = fmaxf(mx.w, w.w); mn.w = fminf(mn.w, w.w);
    }
    float4 gv = *reinterpret_cast<const float4*>(&g[c4]);
    float4 bi = *reinterpret_cast<const float4*>(&bias[c4]);
    float4 bev = *reinterpret_cast<const float4*>(&be[c4]);
    int* Pb = P + b * C + c4;
    { float a = gv.x * BN_SCALE_F; float m = (a >= 0.f) ? mx.x : mn.x;
      float h = fmaxf(fmaf(a, u.x - v.x + m + bi.x, bev.x), 0.f);
      atomicMax(Pb + 0, __float_as_int(h)); }
    { float a = gv.y * BN_SCALE_F; float m = (a >= 0.f) ? mx.y : mn.y;
      float h = fmaxf(fmaf(a, u.y - v.y + m + bi.y, bev.y), 0.f);
      atomicMax(Pb + 1, __float_as_int(h)); }
    { float a = gv.z * BN_SCALE_F; float m = (a >= 0.f) ? mx.z : mn.z;
      float h = fmaxf(fmaf(a, u.z - v.z + m + bi.z, bev.z), 0.f);
      atomicMax(Pb + 2, __float_as_int(h)); }
    { float a = gv.w * BN_SCALE_F; float m = (a >= 0.f) ? mx.w : mn.w;
      float h = fmaxf(fmaf(a, u.w - v.w + m + bi.w, bev.w), 0.f);
      atomicMax(Pb + 3, __float_as_int(h)); }
}

// ---------------- FC head --------------------------------------------------
__global__ __launch_bounds__(256)
void head_kernel(const float* __restrict__ Pp, const float* __restrict__ Wf1,
                 const float* __restrict__ bf1, const float* __restrict__ gf,
                 const float* __restrict__ bef, const float* __restrict__ Wf2,
                 const float* __restrict__ bf2, float* __restrict__ out) {
    __shared__ float ps[256];
    __shared__ float fs[128];
    const int b = blockIdx.x, t = threadIdx.x;
    ps[t] = Pp[b * 256 + t];
    __syncthreads();
    if (t < 128) {
        float acc = bf1[t];
        for (int r = 0; r < 256; ++r) acc += ps[r] * Wf1[r * 128 + t];
        float a = gf[t] * BN_SCALE_F;
        fs[t] = fmaxf(fmaf(a, acc, bef[t]), 0.f);
    }
    __syncthreads();
    if (t < 12) {
        float acc = bf2[t];
        for (int j = 0; j < 128; ++j) acc += fs[j] * Wf2[j * 12 + t];
        out[b * 12 + t] = acc;
    }
}

// ---------------- launch ----------------------------------------------------
extern "C" void kernel_launch(void* const* d_in, const int* in_sizes, int n_in,
                              void* d_out, int out_size) {
    const float* x   = (const float*)d_in[0];
    const float* W1  = (const float*)d_in[1];
    const float* b1  = (const float*)d_in[2];
    const float* g1  = (const float*)d_in[3];
    const float* be1 = (const float*)d_in[4];
    const float* W2  = (const float*)d_in[5];
    const float* b2  = (const float*)d_in[6];
    const float* g2  = (const float*)d_in[7];
    const float* be2 = (const float*)d_in[8];
    const float* W3  = (const float*)d_in[9];
    const float* b3  = (const float*)d_in[10];
    const float* g3  = (const float*)d_in[11];
    const float* be3 = (const float*)d_in[12];
    const float* Wf1 = (const float*)d_in[13];
    const float* bf1 = (const float*)d_in[14];
    const float* gf  = (const float*)d_in[15];
    const float* bef = (const float*)d_in[16];
    const float* Wf2 = (const float*)d_in[17];
    const float* bf2 = (const float*)d_in[18];
    float* out = (float*)d_out;

    float *U, *V, *h1, *h2, *p;
    int* idx;
    cudaGetSymbolAddress((void**)&U,  g_U);
    cudaGetSymbolAddress((void**)&V,  g_V);
    cudaGetSymbolAddress((void**)&h1, g_h1);
    cudaGetSymbolAddress((void**)&h2, g_h2);
    cudaGetSymbolAddress((void**)&idx, g_idx);
    cudaGetSymbolAddress((void**)&p,  g_p);

    cudaFuncSetAttribute(fatL1, cudaFuncAttributeMaxDynamicSharedMemorySize, FAT_SMEM_BYTES);
    cudaFuncSetAttribute(fatL2, cudaFuncAttributeMaxDynamicSharedMemorySize, FAT_SMEM_BYTES);
    cudaFuncSetAttribute(fatL3, cudaFuncAttributeMaxDynamicSharedMemorySize, FAT_SMEM_BYTES);

    cudaMemsetAsync(p, 0, BB * 256 * sizeof(float));   // pool init, up front

    // ---- layer 1: D=6 -> C=64 ----
    fatL1<<<1024 + 1024, 256, FAT_SMEM_BYTES>>>(x, W1, idx, U, V);
    agg_kernel<64><<<MM / 16, 256>>>(U, V, idx, b1, g1, be1, h1);

    // ---- layer 2: D=64 -> C=128 ----
    fatL2<<<1024 + 1024, 256, FAT_SMEM_BYTES>>>(h1, W2, idx, U, V);
    agg_kernel<128><<<MM / 8, 256>>>(U, V, idx, b2, g2, be2, h2);

    // ---- layer 3: D=128 -> C=256 (uv on tf32 tensor cores) ----
    fatL3<<<1024 + 2048, 256, FAT_SMEM_BYTES>>>(h2, W3, idx, U, V);
    agg_pool_kernel<256><<<MM / 4, 256>>>(U, V, idx, b3, g3, be3, (int*)p);

    // ---- head ----
    head_kernel<<<BB, 256>>>(p, Wf1, bf1, gf, bef, Wf2, bf2, out);
}

// round 14
// speedup vs baseline: 1.1110x; 1.1110x over previous
#include <cuda_runtime.h>
#include <math.h>

#define BB 128
#define NN 256
#define MM (BB*NN)
#define KNBR 16
#define BN_SCALE_F 0.99999500003749969f

// ---------------- scratch (device globals; no allocation allowed) ----------
__device__ float g_U[MM * 256];
__device__ float g_V[MM * 256];
__device__ float g_h1[MM * 64];
__device__ float g_h2[MM * 128];
__device__ int   g_idx[MM * KNBR];
__device__ float g_p[BB * 256];

// ---------------- tf32 helpers ---------------------------------------------
__device__ __forceinline__ unsigned f2tf32(float x) {
    unsigned r;
    asm("cvt.rna.tf32.f32 %0, %1;" : "=r"(r) : "f"(x));
    return r;
}

#define MMA_TF32(d0,d1,d2,d3,a0,a1,a2,a3,b0,b1)                               \
  asm volatile("mma.sync.aligned.m16n8k8.row.col.f32.tf32.tf32.f32 "          \
      "{%0,%1,%2,%3}, {%4,%5,%6,%7}, {%8,%9}, {%0,%1,%2,%3};"                 \
      : "+f"(d0), "+f"(d1), "+f"(d2), "+f"(d3)                                \
      : "r"(a0), "r"(a1), "r"(a2), "r"(a3), "r"(b0), "r"(b1))

// ---------------- whole-batch kNN, K=6 padded to 8 (round-1 proven) --------
__global__ __launch_bounds__(256, 1)
void knn6_kernel(const float* __restrict__ X, int* __restrict__ idx_out) {
    __shared__ float Xs[NN * 8];
    __shared__ float sqs[NN];
    const int b = blockIdx.x;
    const int t = threadIdx.x;
    const float* Xb = X + (size_t)b * NN * 6;

    for (int e = t; e < NN * 6; e += 256)
        Xs[(e / 6) * 8 + (e % 6)] = Xb[e];
    Xs[t * 8 + 6] = 0.f; Xs[t * 8 + 7] = 0.f;
    __syncthreads();

    float4 xi0 = *reinterpret_cast<const float4*>(&Xs[t * 8]);
    float4 xi1 = *reinterpret_cast<const float4*>(&Xs[t * 8 + 4]);
    float sq = xi0.x*xi0.x + xi0.y*xi0.y + xi0.z*xi0.z + xi0.w*xi0.w
             + xi1.x*xi1.x + xi1.y*xi1.y;
    sqs[t] = sq;
    __syncthreads();

    float bd[KNBR]; int bj[KNBR];
    #pragma unroll
    for (int s = 0; s < KNBR; ++s) { bd[s] = INFINITY; bj[s] = -1; }

    for (int j = 0; j < NN; ++j) {
        float4 v0 = *reinterpret_cast<const float4*>(&Xs[j * 8]);
        float4 v1 = *reinterpret_cast<const float4*>(&Xs[j * 8 + 4]);
        float dot = xi0.x*v0.x + xi0.y*v0.y + xi0.z*v0.z + xi0.w*v0.w
                  + xi1.x*v1.x + xi1.y*v1.y;
        float d2 = sq + sqs[j] - 2.f * dot;
        if (j != t && d2 < bd[KNBR - 1]) {
            float nd = d2; int nj = j;
            #pragma unroll
            for (int s = 0; s < KNBR; ++s) {
                if (nd < bd[s]) {
                    float td = bd[s]; int tj = bj[s];
                    bd[s] = nd; bj[s] = nj; nd = td; nj = tj;
                }
            }
        }
    }
    #pragma unroll
    for (int s = 0; s < KNBR; ++s)
        idx_out[((size_t)b * NN + t) * KNBR + s] = bj[s];
}

// ---------------- whole-batch kNN (round-1 proven): one block per batch ----
template<int D, int P>
__global__ __launch_bounds__(256, 1)
void knn_kernel(const float* __restrict__ X, int* __restrict__ idx_out) {
    extern __shared__ float sm[];
    float* Xs  = sm;            // [256 * P]
    float* sqs = sm + NN * P;   // [256]
    const int b = blockIdx.x;
    const int t = threadIdx.x;
    const float* Xb = X + (size_t)b * NN * D;

    for (int e = t; e < NN * D; e += 256)
        Xs[(e / D) * P + (e % D)] = Xb[e];
    #pragma unroll
    for (int c = D; c < P; ++c) Xs[t * P + c] = 0.f;
    __syncthreads();

    constexpr int Q = P / 4;
    float4 xi[Q];
    #pragma unroll
    for (int q = 0; q < Q; ++q)
        xi[q] = *reinterpret_cast<const float4*>(&Xs[t * P + 4 * q]);
    float sq = 0.f;
    #pragma unroll
    for (int q = 0; q < Q; ++q)
        sq += xi[q].x * xi[q].x + xi[q].y * xi[q].y + xi[q].z * xi[q].z + xi[q].w * xi[q].w;
    sqs[t] = sq;
    __syncthreads();

    float bd[KNBR];
    int   bj[KNBR];
    #pragma unroll
    for (int s = 0; s < KNBR; ++s) { bd[s] = INFINITY; bj[s] = -1; }

    for (int j = 0; j < NN; ++j) {
        const float4* xj = reinterpret_cast<const float4*>(&Xs[j * P]);
        float dx = 0.f, dy = 0.f, dz = 0.f, dw = 0.f;
        #pragma unroll
        for (int q = 0; q < Q; ++q) {
            float4 v = xj[q];            // broadcast LDS.128
            dx += xi[q].x * v.x;
            dy += xi[q].y * v.y;
            dz += xi[q].z * v.z;
            dw += xi[q].w * v.w;
        }
        float dot = (dx + dy) + (dz + dw);
        float d2 = sq + sqs[j] - 2.f * dot;
        if (j != t && d2 < bd[KNBR - 1]) {
            float nd = d2; int nj = j;
            #pragma unroll
            for (int s = 0; s < KNBR; ++s) {   // stable sorted insert
                if (nd < bd[s]) {
                    float td = bd[s]; int tj = bj[s];
                    bd[s] = nd; bj[s] = nj; nd = td; nj = tj;
                }
            }
        }
    }
    #pragma unroll
    for (int s = 0; s < KNBR; ++s)
        idx_out[((size_t)b * NN + t) * KNBR + s] = bj[s];
}

// ---------------- layer-1 U/V GEMM (K=6, C=64): tiny, direct ---------------
__global__ __launch_bounds__(256)
void uv_gemm1_kernel(const float* __restrict__ X, const float* __restrict__ W,
                     float* __restrict__ U, float* __restrict__ V) {
    __shared__ float Ws[12][64];
    int t = threadIdx.x;
    for (int e = t; e < 12 * 64; e += 256) Ws[e / 64][e % 64] = W[e];
    __syncthreads();
    int m = blockIdx.x * 4 + (t >> 6);
    int c = t & 63;
    const float* x = X + (size_t)m * 6;
    float u = 0.f, v = 0.f;
    #pragma unroll
    for (int d = 0; d < 6; ++d) {
        float xd = x[d];
        u += xd * Ws[d][c];
        v += xd * Ws[6 + d][c];
    }
    U[(size_t)m * 64 + c] = u;
    V[(size_t)m * 64 + c] = v;
}

// ---- uv2 fp32: BM=128 BN=128 BK=8, 8x8/thread, double-buffered ------------
template<int K>
__global__ __launch_bounds__(256)
void uv8_kernel(const float* __restrict__ X, const float* __restrict__ W,
                const int C, float* __restrict__ U, float* __restrict__ V) {
    extern __shared__ float sm[];
    float* As = sm;                  // [2][8][132]
    float* Wt = sm + 2112;           // [2][8][132]
    const int t = threadIdx.x;
    const int m0 = blockIdx.x * 128;
    const int nt = C / 128;
    const bool isU = (int)blockIdx.y < nt;
    const int n0 = (isU ? blockIdx.y : blockIdx.y - nt) * 128;
    const float* Wb = W + (isU ? (size_t)0 : (size_t)K * C);
    float* Out = isU ? U : V;

    const int am = t >> 1, ak = (t & 1) * 4;
    const int wk = t >> 5, wn = (t & 31) * 4;
    const int tx = t & 15, ty = t >> 4;

    float acc[8][8] = {};

    auto stage = [&](int buf, const float4& xa, const float4& wa) {
        float* A = As + buf * 1056;
        A[(ak + 0) * 132 + am] = xa.x; A[(ak + 1) * 132 + am] = xa.y;
        A[(ak + 2) * 132 + am] = xa.z; A[(ak + 3) * 132 + am] = xa.w;
        *reinterpret_cast<float4*>(&Wt[buf * 1056 + wk * 132 + wn]) = wa;
    };
    auto compute = [&](int pb) {
        const float* A = As + pb * 1056;
        const float* Wp = Wt + pb * 1056;
        #pragma unroll
        for (int k = 0; k < 8; ++k) {
            float4 a0 = *reinterpret_cast<const float4*>(&A[k * 132 + ty * 8]);
            float4 a1 = *reinterpret_cast<const float4*>(&A[k * 132 + ty * 8 + 4]);
            float4 b0 = *reinterpret_cast<const float4*>(&Wp[k * 132 + tx * 4]);
            float4 b1 = *reinterpret_cast<const float4*>(&Wp[k * 132 + 64 + tx * 4]);
            float av[8] = {a0.x, a0.y, a0.z, a0.w, a1.x, a1.y, a1.z, a1.w};
            float bv[8] = {b0.x, b0.y, b0.z, b0.w, b1.x, b1.y, b1.z, b1.w};
            #pragma unroll
            for (int i = 0; i < 8; ++i) {
                #pragma unroll
                for (int c = 0; c < 8; ++c)
                    acc[i][c] += av[i] * bv[c];
            }
        }
    };

    float4 xa = *reinterpret_cast<const float4*>(&X[(size_t)(m0 + am) * K + ak]);
    float4 wa = *reinterpret_cast<const float4*>(&Wb[(size_t)wk * C + n0 + wn]);
    stage(0, xa, wa);
    __syncthreads();

    const int NCH = K / 8;
    for (int ci = 1; ci < NCH; ++ci) {
        float4 xn = *reinterpret_cast<const float4*>(
            &X[(size_t)(m0 + am) * K + ci * 8 + ak]);
        float4 wnx = *reinterpret_cast<const float4*>(
            &Wb[(size_t)(ci * 8 + wk) * C + n0 + wn]);
        compute((ci - 1) & 1);
        stage(ci & 1, xn, wnx);
        __syncthreads();
    }
    compute((NCH - 1) & 1);

    #pragma unroll
    for (int i = 0; i < 8; ++i) {
        float* dst = &Out[(size_t)(m0 + ty * 8 + i) * C + n0 + tx * 4];
        *reinterpret_cast<float4*>(dst) =
            make_float4(acc[i][0], acc[i][1], acc[i][2], acc[i][3]);
        *reinterpret_cast<float4*>(dst + 64) =
            make_float4(acc[i][4], acc[i][5], acc[i][6], acc[i][7]);
    }
}

// ---- uv3 tf32 tensor-core kernel: K=128, C=256, BM=128, BN=64 -------------
// U/V feed only the final agg+pool (no downstream kNN); 1xTF32 proven at
// rel_err 1.78e-4 in rounds 12/13.
__global__ __launch_bounds__(256)
void uv3_tf32_kernel(const float* __restrict__ X, const float* __restrict__ W,
                     float* __restrict__ U, float* __restrict__ V) {
    extern __shared__ float smf[];
    constexpr int K = 128, C = 256;
    unsigned* As = reinterpret_cast<unsigned*>(smf);          // [2][8][132]
    unsigned* Wt = reinterpret_cast<unsigned*>(smf) + 2112;   // [2][8][68]
    const int t = threadIdx.x;
    const int m0 = blockIdx.x * 128;
    const int by = blockIdx.y;
    const bool isU = by < 4;
    const int n0 = (by & 3) * 64;
    const float* Wb = W + (isU ? (size_t)0 : (size_t)K * C);
    float* Out = isU ? U : V;

    const int am = t >> 1, ak = (t & 1) * 4;
    const int wk = t >> 4, wn2 = (t & 15) * 4;
    const int lane = t & 31, warp = t >> 5;
    const int gid = lane >> 2, tid4 = lane & 3;
    const int wm = (warp >> 1) * 32, wn = (warp & 1) * 32;

    float acc[2][4][4] = {};

    auto stage = [&](int buf, const float4& xa, const float4& wa) {
        unsigned* A = As + buf * 1056;
        A[(ak + 0) * 132 + am] = f2tf32(xa.x);
        A[(ak + 1) * 132 + am] = f2tf32(xa.y);
        A[(ak + 2) * 132 + am] = f2tf32(xa.z);
        A[(ak + 3) * 132 + am] = f2tf32(xa.w);
        if (t < 128) {
            unsigned* Wp = Wt + buf * 544 + wk * 68 + wn2;
            Wp[0] = f2tf32(wa.x); Wp[1] = f2tf32(wa.y);
            Wp[2] = f2tf32(wa.z); Wp[3] = f2tf32(wa.w);
        }
    };
    auto compute = [&](int pb) {
        const unsigned* A = As + pb * 1056;
        const unsigned* Wp = Wt + pb * 544;
        unsigned a[2][4], bf[4][2];
        #pragma unroll
        for (int mi = 0; mi < 2; ++mi) {
            const int base = wm + mi * 16 + gid;
            a[mi][0] = A[tid4 * 132 + base];
            a[mi][1] = A[tid4 * 132 + base + 8];
            a[mi][2] = A[(tid4 + 4) * 132 + base];
            a[mi][3] = A[(tid4 + 4) * 132 + base + 8];
        }
        #pragma unroll
        for (int ni = 0; ni < 4; ++ni) {
            const int bc = wn + ni * 8 + gid;
            bf[ni][0] = Wp[tid4 * 68 + bc];
            bf[ni][1] = Wp[(tid4 + 4) * 68 + bc];
        }
        #pragma unroll
        for (int mi = 0; mi < 2; ++mi)
            #pragma unroll
            for (int ni = 0; ni < 4; ++ni)
                MMA_TF32(acc[mi][ni][0], acc[mi][ni][1],
                         acc[mi][ni][2], acc[mi][ni][3],
                         a[mi][0], a[mi][1], a[mi][2], a[mi][3],
                         bf[ni][0], bf[ni][1]);
    };

    float4 xa = *reinterpret_cast<const float4*>(&X[(size_t)(m0 + am) * K + ak]);
    float4 wa = (t < 128)
        ? *reinterpret_cast<const float4*>(&Wb[(size_t)wk * C + n0 + wn2])
        : make_float4(0.f, 0.f, 0.f, 0.f);
    stage(0, xa, wa);
    __syncthreads();

    const int NCH = K / 8;
    for (int ci = 1; ci < NCH; ++ci) {
        float4 xn = *reinterpret_cast<const float4*>(
            &X[(size_t)(m0 + am) * K + ci * 8 + ak]);
        float4 wnx = (t < 128)
            ? *reinterpret_cast<const float4*>(&Wb[(size_t)(ci * 8 + wk) * C + n0 + wn2])
            : make_float4(0.f, 0.f, 0.f, 0.f);
        compute((ci - 1) & 1);
        stage(ci & 1, xn, wnx);
        __syncthreads();
    }
    compute((NCH - 1) & 1);

    #pragma unroll
    for (int mi = 0; mi < 2; ++mi) {
        #pragma unroll
        for (int ni = 0; ni < 4; ++ni) {
            const int row = m0 + wm + mi * 16 + gid;
            const int col = n0 + wn + ni * 8 + tid4 * 2;
            *reinterpret_cast<float2*>(&Out[(size_t)row * C + col]) =
                make_float2(acc[mi][ni][0], acc[mi][ni][1]);
            *reinterpret_cast<float2*>(&Out[(size_t)(row + 8) * C + col]) =
                make_float2(acc[mi][ni][2], acc[mi][ni][3]);
        }
    }
}

// -------- neighbor aggregation + BN + ReLU: float4, 4 channels/thread ------
template<int C>
__global__ __launch_bounds__(256)
void agg_kernel(const float* __restrict__ U, const float* __restrict__ V,
                const int* __restrict__ idx, const float* __restrict__ bias,
                const float* __restrict__ g, const float* __restrict__ be,
                float* __restrict__ H) {
    constexpr int CG = C / 4;
    constexpr int PPB = 256 / CG;
    __shared__ int sidx[PPB * KNBR];
    const int p0 = blockIdx.x * PPB;
    const int t = threadIdx.x;
    if (t < PPB * KNBR) sidx[t] = idx[(size_t)p0 * KNBR + t] * C;
    __syncthreads();
    const int lp = t / CG, c4 = (t % CG) * 4;
    const int pt = p0 + lp;
    const int b = pt >> 8;
    const float* Vb4 = V + ((size_t)(b << 8)) * C + c4;
    float4 u = *reinterpret_cast<const float4*>(&U[(size_t)pt * C + c4]);
    float4 v = *reinterpret_cast<const float4*>(&V[(size_t)pt * C + c4]);
    float4 mx = make_float4(-INFINITY, -INFINITY, -INFINITY, -INFINITY);
    float4 mn = make_float4(INFINITY, INFINITY, INFINITY, INFINITY);
    #pragma unroll
    for (int k = 0; k < KNBR; ++k) {
        float4 w = *reinterpret_cast<const float4*>(Vb4 + sidx[lp * KNBR + k]);
        mx.x = fmaxf(mx.x, w.x); mn.x = fminf(mn.x, w.x);
        mx.y = fmaxf(mx.y, w.y); mn.y = fminf(mn.y, w.y);
        mx.z = fmaxf(mx.z, w.z); mn.z = fminf(mn.z, w.z);
        mx.w = fmaxf(mx.w, w.w); mn.w = fminf(mn.w, w.w);
    }
    float4 gv = *reinterpret_cast<const float4*>(&g[c4]);
    float4 bi = *reinterpret_cast<const float4*>(&bias[c4]);
    float4 bev = *reinterpret_cast<const float4*>(&be[c4]);
    float4 o;
    { float a = gv.x * BN_SCALE_F; float m = (a >= 0.f) ? mx.x : mn.x;
      o.x = fmaxf(fmaf(a, u.x - v.x + m + bi.x, bev.x), 0.f); }
    { float a = gv.y * BN_SCALE_F; float m = (a >= 0.f) ? mx.y : mn.y;
      o.y = fmaxf(fmaf(a, u.y - v.y + m + bi.y, bev.y), 0.f); }
    { float a = gv.z * BN_SCALE_F; float m = (a >= 0.f) ? mx.z : mn.z;
      o.z = fmaxf(fmaf(a, u.z - v.z + m + bi.z, bev.z), 0.f); }
    { float a = gv.w * BN_SCALE_F; float m = (a >= 0.f) ? mx.w : mn.w;
      o.w = fmaxf(fmaf(a, u.w - v.w + m + bi.w, bev.w), 0.f); }
    *reinterpret_cast<float4*>(&H[(size_t)pt * C + c4]) = o;
}

// ------- layer-3 agg + global max pool (h >= 0), float4 --------------------
template<int C>
__global__ __launch_bounds__(256)
void agg_pool_kernel(const float* __restrict__ U, const float* __restrict__ V,
                     const int* __restrict__ idx, const float* __restrict__ bias,
                     const float* __restrict__ g, const float* __restrict__ be,
                     int* __restrict__ P) {
    constexpr int CG = C / 4;
    constexpr int PPB = 256 / CG;
    __shared__ int sidx[PPB * KNBR];
    const int p0 = blockIdx.x * PPB;
    const int t = threadIdx.x;
    if (t < PPB * KNBR) sidx[t] = idx[(size_t)p0 * KNBR + t] * C;
    __syncthreads();
    const int lp = t / CG, c4 = (t % CG) * 4;
    const int pt = p0 + lp;
    const int b = pt >> 8;
    const float* Vb4 = V + ((size_t)(b << 8)) * C + c4;
    float4 u = *reinterpret_cast<const float4*>(&U[(size_t)pt * C + c4]);
    float4 v = *reinterpret_cast<const float4*>(&V[(size_t)pt * C + c4]);
    float4 mx = make_float4(-INFINITY, -INFINITY, -INFINITY, -INFINITY);
    float4 mn = make_float4(INFINITY, INFINITY, INFINITY, INFINITY);
    #pragma unroll
    for (int k = 0; k < KNBR; ++k) {
        float4 w = *reinterpret_cast<const float4*>(Vb4 + sidx[lp * KNBR + k]);
        mx.x = fmaxf(mx.x, w.x); mn.x = fminf(mn.x, w.x);
        mx.y = fmaxf(mx.y, w.y); mn.y = fminf(mn.y, w.y);
        mx.z = fmaxf(mx.z, w.z); mn.z = fminf(mn.z, w.z);
        mx.w = fmaxf(mx.w, w.w); mn.w = fminf(mn.w, w.w);
    }
    float4 gv = *reinterpret_cast<const float4*>(&g[c4]);
    float4 bi = *reinterpret_cast<const float4*>(&bias[c4]);
    float4 bev = *reinterpret_cast<const float4*>(&be[c4]);
    int* Pb = P + b * C + c4;
    { float a = gv.x * BN_SCALE_F; float m = (a >= 0.f) ? mx.x : mn.x;
      float h = fmaxf(fmaf(a, u.x - v.x + m + bi.x, bev.x), 0.f);
      atomicMax(Pb + 0, __float_as_int(h)); }
    { float a = gv.y * BN_SCALE_F; float m = (a >= 0.f) ? mx.y : mn.y;
      float h = fmaxf(fmaf(a, u.y - v.y + m + bi.y, bev.y), 0.f);
      atomicMax(Pb + 1, __float_as_int(h)); }
    { float a = gv.z * BN_SCALE_F; float m = (a >= 0.f) ? mx.z : mn.z;
      float h = fmaxf(fmaf(a, u.z - v.z + m + bi.z, bev.z), 0.f);
      atomicMax(Pb + 2, __float_as_int(h)); }
    { float a = gv.w * BN_SCALE_F; float m = (a >= 0.f) ? mx.w : mn.w;
      float h = fmaxf(fmaf(a, u.w - v.w + m + bi.w, bev.w), 0.f);
      atomicMax(Pb + 3, __float_as_int(h)); }
}

// ---------------- FC head --------------------------------------------------
__global__ __launch_bounds__(256)
void head_kernel(const float* __restrict__ Pp, const float* __restrict__ Wf1,
                 const float* __restrict__ bf1, const float* __restrict__ gf,
                 const float* __restrict__ bef, const float* __restrict__ Wf2,
                 const float* __restrict__ bf2, float* __restrict__ out) {
    __shared__ float ps[256];
    __shared__ float fs[128];
    const int b = blockIdx.x, t = threadIdx.x;
    ps[t] = Pp[b * 256 + t];
    __syncthreads();
    if (t < 128) {
        float acc = bf1[t];
        for (int r = 0; r < 256; ++r) acc += ps[r] * Wf1[r * 128 + t];
        float a = gf[t] * BN_SCALE_F;
        fs[t] = fmaxf(fmaf(a, acc, bef[t]), 0.f);
    }
    __syncthreads();
    if (t < 12) {
        float acc = bf2[t];
        for (int j = 0; j < 128; ++j) acc += fs[j] * Wf2[j * 12 + t];
        out[b * 12 + t] = acc;
    }
}

// ---------------- launch ----------------------------------------------------
extern "C" void kernel_launch(void* const* d_in, const int* in_sizes, int n_in,
                              void* d_out, int out_size) {
    const float* x   = (const float*)d_in[0];
    const float* W1  = (const float*)d_in[1];
    const float* b1  = (const float*)d_in[2];
    const float* g1  = (const float*)d_in[3];
    const float* be1 = (const float*)d_in[4];
    const float* W2  = (const float*)d_in[5];
    const float* b2  = (const float*)d_in[6];
    const float* g2  = (const float*)d_in[7];
    const float* be2 = (const float*)d_in[8];
    const float* W3  = (const float*)d_in[9];
    const float* b3  = (const float*)d_in[10];
    const float* g3  = (const float*)d_in[11];
    const float* be3 = (const float*)d_in[12];
    const float* Wf1 = (const float*)d_in[13];
    const float* bf1 = (const float*)d_in[14];
    const float* gf  = (const float*)d_in[15];
    const float* bef = (const float*)d_in[16];
    const float* Wf2 = (const float*)d_in[17];
    const float* bf2 = (const float*)d_in[18];
    float* out = (float*)d_out;

    float *U, *V, *h1, *h2, *p;
    int* idx;
    cudaGetSymbolAddress((void**)&U,  g_U);
    cudaGetSymbolAddress((void**)&V,  g_V);
    cudaGetSymbolAddress((void**)&h1, g_h1);
    cudaGetSymbolAddress((void**)&h2, g_h2);
    cudaGetSymbolAddress((void**)&idx, g_idx);
    cudaGetSymbolAddress((void**)&p,  g_p);

    const int smem64  = (NN * 68  + NN) * 4;   //  70,656
    const int smem128 = (NN * 132 + NN) * 4;   // 136,192
    const int smemUV8 = 4224 * 4;              //  16,896
    const int smemTF  = 3200 * 4;              //  12,800
    cudaFuncSetAttribute(knn_kernel<64, 68>,
                         cudaFuncAttributeMaxDynamicSharedMemorySize, smem64);
    cudaFuncSetAttribute(knn_kernel<128, 132>,
                         cudaFuncAttributeMaxDynamicSharedMemorySize, smem128);

    cudaMemsetAsync(p, 0, BB * 256 * sizeof(float));   // pool init, up front

    // ---- layer 1: D=6 -> C=64 ----
    knn6_kernel<<<BB, 256>>>(x, idx);
    uv_gemm1_kernel<<<MM / 4, 256>>>(x, W1, U, V);
    agg_kernel<64><<<MM / 16, 256>>>(U, V, idx, b1, g1, be1, h1);

    // ---- layer 2: D=64 -> C=128 ----
    knn_kernel<64, 68><<<BB, 256, smem64>>>(h1, idx);
    uv8_kernel<64><<<dim3(MM / 128, 2), 256, smemUV8>>>(h1, W2, 128, U, V);
    agg_kernel<128><<<MM / 8, 256>>>(U, V, idx, b2, g2, be2, h2);

    // ---- layer 3: D=128 -> C=256 (uv on tf32 tensor cores) ----
    knn_kernel<128, 132><<<BB, 256, smem128>>>(h2, idx);
    uv3_tf32_kernel<<<dim3(MM / 128, 8), 256, smemTF>>>(h2, W3, U, V);
    agg_pool_kernel<256><<<MM / 4, 256>>>(U, V, idx, b3, g3, be3, (int*)p);

    // ---- head ----
    head_kernel<<<BB, 256>>>(p, Wf1, bf1, gf, bef, Wf2, bf2, out);
}